// round 12
// baseline (speedup 1.0000x reference)
#include <cuda_runtime.h>
#include <cstdint>

#define B_      32
#define T_      512
#define D_      384
#define MAXOUT  3584                    // T_ * (8 - 1)
#define VEC     (D_ / 4)                // 96 float4 per row
#define U32ROW  (VEC / 2)               // 48 32B-units per row
#define THREADS 256
#define UNROLL  4                       // 32B units per thread (same 128B/thread)
#define U_PER_BLOCK (THREADS * UNROLL)  // 1024 units = 2048 float4
#define U_PER_BATCH (MAXOUT * U32ROW)   // 172032
#define BLOCKS_PER_BATCH (U_PER_BATCH / U_PER_BLOCK) // 168, exact
#define NROWS   24                      // distinct output rows per block (22) + pad

// 256-bit read-only gather with keep-in-L2 priority: biases LRU so the 25 MB
// input survives the 176 MB/replay evict-first write stream and stays
// L2-resident across graph replays.
__device__ __forceinline__ void ldg_keep32(const float4* p, float4& a, float4& b) {
    asm volatile("ld.global.nc.L2::evict_last.v8.b32 "
                 "{%0,%1,%2,%3,%4,%5,%6,%7}, [%8];"
                 : "=f"(a.x), "=f"(a.y), "=f"(a.z), "=f"(a.w),
                   "=f"(b.x), "=f"(b.y), "=f"(b.z), "=f"(b.w) : "l"(p));
}

__global__ void __launch_bounds__(THREADS) lr_fused_kernel(
    const int*    __restrict__ dur,
    const float4* __restrict__ in,
    float4*       __restrict__ out)
{
    __shared__ int cum[T_];
    __shared__ int wsum[8];
    __shared__ int s_idx[NROWS];

    const int tid = threadIdx.x;
    const int b   = blockIdx.y;

    // ── Per-block recomputed inclusive scan of this batch's 512 durations ──
    const int2 dp = ((const int2*)(dur + b * T_))[tid];
    const int  d0 = max(dp.x, 0);
    const int  d1 = max(dp.y, 0);

    const int lane = tid & 31;
    const int warp = tid >> 5;

    int v = d0 + d1;
    #pragma unroll
    for (int o = 1; o < 32; o <<= 1) {
        int n = __shfl_up_sync(0xffffffffu, v, o);
        if (lane >= o) v += n;
    }
    if (lane == 31) wsum[warp] = v;
    __syncthreads();
    if (warp == 0) {
        int w = (lane < 8) ? wsum[lane] : 0;
        #pragma unroll
        for (int o = 1; o < 8; o <<= 1) {
            int n = __shfl_up_sync(0xffffffffu, w, o);
            if (lane >= o) w += n;
        }
        if (lane < 8) wsum[lane] = w;
    }
    __syncthreads();

    const int incl = v + (warp > 0 ? wsum[warp - 1] : 0);
    cum[2 * tid + 1] = incl;
    cum[2 * tid]     = incl - d1;
    __syncthreads();

    const int total    = cum[T_ - 1];
    const int u_base   = blockIdx.x * U_PER_BLOCK;
    const int row_base = u_base / U32ROW;

    // ── One binary search per distinct output row ──
    if (tid < NROWS) {
        const int row = row_base + tid;
        int idx = -1;
        if (row < total) {
            int p = 0;
            #pragma unroll
            for (int step = 256; step > 0; step >>= 1)
                if (cum[p + step - 1] <= row) p += step;
            idx = min(p, T_ - 1);
        }
        s_idx[tid] = idx;
    }
    __syncthreads();

    const int posu = u_base + tid;
    const float4* __restrict__ inb  = in  + b * (T_ * VEC);
    float4*       __restrict__ outb = out + b * (MAXOUT * VEC);

    if (row_base >= total) {
        // Entire block past the valid region: pure zero fill.
        const float4 z = make_float4(0.f, 0.f, 0.f, 0.f);
        #pragma unroll
        for (int j = 0; j < UNROLL; ++j) {
            const int f4 = (posu + j * THREADS) * 2;
            __stcs(&outb[f4],     z);
            __stcs(&outb[f4 + 1], z);
        }
        return;
    }

    int idx[UNROLL], col[UNROLL];
    #pragma unroll
    for (int j = 0; j < UNROLL; ++j) {
        const int pu  = posu + j * THREADS;
        const int row = pu / U32ROW;
        col[j] = pu - row * U32ROW;          // 32B column within row
        idx[j] = s_idx[row - row_base];
    }

    // Unconditional clamped gathers: 4 independent keep-in-L2 LDG.256s.
    float4 va[UNROLL], vb[UNROLL];
    #pragma unroll
    for (int j = 0; j < UNROLL; ++j) {
        const int ic = max(idx[j], 0);
        ldg_keep32(&inb[ic * VEC + col[j] * 2], va[j], vb[j]);
    }

    asm volatile("" ::: "memory");

    #pragma unroll
    for (int j = 0; j < UNROLL; ++j) {
        float4 a = va[j], b4 = vb[j];
        if (idx[j] < 0) {
            a  = make_float4(0.f, 0.f, 0.f, 0.f);
            b4 = make_float4(0.f, 0.f, 0.f, 0.f);
        }
        const int f4 = (posu + j * THREADS) * 2;
        __stcs(&outb[f4],     a);
        __stcs(&outb[f4 + 1], b4);
    }
}

extern "C" void kernel_launch(void* const* d_in, const int* in_sizes, int n_in,
                              void* d_out, int out_size)
{
    const float* x   = (const float*)d_in[0];   // [B, T, D] float32
    const int*   dur = (const int*)d_in[1];     // [B, T] int32
    float* out = (float*)d_out;                 // [B, MAXOUT, D] float32

    dim3 grid(BLOCKS_PER_BATCH, B_);
    lr_fused_kernel<<<grid, THREADS>>>(dur, (const float4*)x, (float4*)out);
}

// round 13
// speedup vs baseline: 1.4098x; 1.4098x over previous
#include <cuda_runtime.h>

#define B_      32
#define T_      512
#define D_      384
#define MAXOUT  3584                    // T_ * (8 - 1)
#define VEC     (D_ / 4)                // 96 float4 per row
#define THREADS 256
#define UNROLL  8
#define F4_PER_BATCH (MAXOUT * VEC)     // 344064
#define F4_PER_BLOCK (THREADS * UNROLL) // 2048
#define BLOCKS_PER_BATCH (F4_PER_BATCH / F4_PER_BLOCK) // 168, exact
#define NROWS   24                      // distinct output rows per block (22) + pad

// Champion formulation (R5): fully fused single launch.
// - per-block recomputed scan of the 512 durations (L2-hot, ~free)
// - one binary search per distinct output row -> smem table
// - 8-deep batched clamped gathers (cached: input reused ~3.5x via L1/L2)
// - streaming .cs stores (write-once output, don't pollute L2)
// - store-only fast path for blocks entirely past `total`
__global__ void __launch_bounds__(THREADS) lr_fused_kernel(
    const int*    __restrict__ dur,
    const float4* __restrict__ in,
    float4*       __restrict__ out)
{
    __shared__ int cum[T_];
    __shared__ int wsum[8];
    __shared__ int s_idx[NROWS];

    const int tid = threadIdx.x;
    const int b   = blockIdx.y;

    // ── Per-block recomputed inclusive scan of this batch's 512 durations ──
    const int2 dp = ((const int2*)(dur + b * T_))[tid];
    const int  d0 = max(dp.x, 0);
    const int  d1 = max(dp.y, 0);

    const int lane = tid & 31;
    const int warp = tid >> 5;

    int v = d0 + d1;
    #pragma unroll
    for (int o = 1; o < 32; o <<= 1) {
        int n = __shfl_up_sync(0xffffffffu, v, o);
        if (lane >= o) v += n;
    }
    if (lane == 31) wsum[warp] = v;
    __syncthreads();
    if (warp == 0) {
        int w = (lane < 8) ? wsum[lane] : 0;
        #pragma unroll
        for (int o = 1; o < 8; o <<= 1) {
            int n = __shfl_up_sync(0xffffffffu, w, o);
            if (lane >= o) w += n;
        }
        if (lane < 8) wsum[lane] = w;
    }
    __syncthreads();

    const int incl = v + (warp > 0 ? wsum[warp - 1] : 0);
    cum[2 * tid + 1] = incl;
    cum[2 * tid]     = incl - d1;
    __syncthreads();

    const int total    = cum[T_ - 1];
    const int f4_base  = blockIdx.x * F4_PER_BLOCK;
    const int row_base = f4_base / VEC;

    // ── One binary search per distinct output row ──
    if (tid < NROWS) {
        const int row = row_base + tid;
        int idx = -1;
        if (row < total) {
            int p = 0;
            #pragma unroll
            for (int step = 256; step > 0; step >>= 1)
                if (cum[p + step - 1] <= row) p += step;
            idx = min(p, T_ - 1);
        }
        s_idx[tid] = idx;
    }
    __syncthreads();

    const int posb = f4_base + tid;
    const float4* __restrict__ inb  = in  + b * (T_ * VEC);
    float4*       __restrict__ outb = out + b * F4_PER_BATCH;

    if (row_base >= total) {
        // Entire block past the valid region: pure zero fill.
        const float4 z = make_float4(0.f, 0.f, 0.f, 0.f);
        #pragma unroll
        for (int j = 0; j < UNROLL; ++j)
            __stcs(&outb[posb + j * THREADS], z);
        return;
    }

    int idx[UNROLL], col[UNROLL];
    #pragma unroll
    for (int j = 0; j < UNROLL; ++j) {
        const int pos = posb + j * THREADS;
        const int row = pos / VEC;
        col[j] = pos - row * VEC;
        idx[j] = s_idx[row - row_base];
    }

    // Unconditional clamped gathers: 8 independent LDG.128s.
    float4 val[UNROLL];
    #pragma unroll
    for (int j = 0; j < UNROLL; ++j) {
        const int ic = max(idx[j], 0);
        val[j] = __ldg(&inb[ic * VEC + col[j]]);
    }

    #pragma unroll
    for (int j = 0; j < UNROLL; ++j) {
        float4 v4 = val[j];
        if (idx[j] < 0) v4 = make_float4(0.f, 0.f, 0.f, 0.f);
        __stcs(&outb[posb + j * THREADS], v4);
    }
}

extern "C" void kernel_launch(void* const* d_in, const int* in_sizes, int n_in,
                              void* d_out, int out_size)
{
    const float* x   = (const float*)d_in[0];   // [B, T, D] float32
    const int*   dur = (const int*)d_in[1];     // [B, T] int32
    float* out = (float*)d_out;                 // [B, MAXOUT, D] float32

    dim3 grid(BLOCKS_PER_BATCH, B_);
    lr_fused_kernel<<<grid, THREADS>>>(dur, (const float4*)x, (float4*)out);
}